// round 14
// baseline (speedup 1.0000x reference)
#include <cuda_runtime.h>
#include <stdint.h>
#include <math.h>

#define THRESH 1e-4f
#define MAXBP  8192
#define BIGL   0x40000000

// ---- kA config ----
#define BLKA 256
#define CHA  9                      // odd stride -> conflict-free smem chain reads
#define WUP  24
#define TILE (BLKA*CHA)             // 2304
#define XN   (TILE + WUP + 32)      // 2360
#define SZN  (TILE + 32)            // 2336
// box-screen constants: TH^(1/6)*0.997 and TH^(1/5)*1.02
#define C6BOX 0.212742f
#define C5BOX 0.161659f

// ---- k4 config ----
#define KBLK  256
#define NT    256                   // steps per tile (R7-proven)
#define HALO4 8
#define NIN   (NT + HALO4)
#define SLOT(i) ((i) ^ (((i) >> 3) & 7))   // float4-slot swizzle (R7/R8-verified)
#define BPSM  6
#define NSM   148

// Scratch (no allocations); zero-init first run, self-reset for graph replays.
__device__ int g_anom_n = 0;
__device__ int g_ticket = 0;
__device__ int g_anom_p[MAXBP];
__device__ int g_anom_l[MAXBP];
__device__ int g_K;
__device__ int g_P[MAXBP];
__device__ int g_Q[MAXBP];
__device__ float g_C[8];            // w2, w4_2, dt1, dt2, d2t1, d2t2

// ============================================================================
// kA: fused Z-scan + box-screened anomaly scan + orbit walk (R13-proven).
// ============================================================================
__global__ __launch_bounds__(BLKA) void kA(const float* __restrict__ X,
                                           const float* __restrict__ pr,
                                           float* __restrict__ Z, int T) {
    __shared__ float sCC[XN];
    __shared__ float sZ[SZN];
    __shared__ float sC[4];
    int nsteps = T - 1;
    int B = blockIdx.x * TILE;
    int tid = threadIdx.x;

    if (tid == 0) {                 // tanh(double) ONCE per block
        sC[0] = (float)tanh((double)pr[0]);
        sC[1] = (float)tanh((double)pr[1]);
        sC[2] = pr[2];
        sC[3] = pr[3];
    }
    __syncthreads();
    float w1 = sC[0], w2 = sC[1], w3 = sC[2], w4 = sC[3];
    float w4_2 = 2.0f * w4;

    for (int i = tid; i < XN; i += BLKA) {       // stage cc coalesced, 0-padded
        int t = B - WUP + i;
        float x = (t >= 0 && t < T) ? X[t] : 0.f;
        sCC[i] = fmaf(w3, x * x, w1 * x);
    }
    __syncthreads();

    // ---- phase 1: fixed-trip h chain (cc=0 pad keeps h exactly 0) ----
    {
        int base = tid * CHA;
        float h = 0.f;
#pragma unroll
        for (int j = 0; j < WUP; ++j) {
            float u = fmaf(w4, h, w2);
            h = fmaf(h, u, sCC[base + j]);
        }
        sZ[base] = h;
#pragma unroll
        for (int j = 0; j < CHA; ++j) {
            float u = fmaf(w4, h, w2);
            h = fmaf(h, u, sCC[base + WUP + j]);
            sZ[base + 1 + j] = h;
        }
        if (tid == BLKA - 1) {                   // 31-step halo
#pragma unroll
            for (int j = 0; j < 31; ++j) {
                float u = fmaf(w4, h, w2);
                h = fmaf(h, u, sCC[base + WUP + CHA + j]);
                sZ[base + CHA + 1 + j] = h;
            }
        }
    }
    __syncthreads();

    if (B == 0 && tid == 0) Z[0] = 0.f;          // coalesced Z writeout
    for (int i = tid; i < TILE; i += BLKA) {
        int g = B + 1 + i;
        if (g <= nsteps) Z[g] = sZ[1 + i];
    }

    // ---- phase 2: box-screened anomaly scan ----
    float HHI, HLO;
    if (w4_2 > 0.f) { HHI = (C6BOX - w2) / w4_2; HLO = (C5BOX - w2) / w4_2; }
    else            { HHI = -1e30f; HLO = 1e30f; }
    int si = B + tid * CHA;
    if (si < nsteps) {
        int pe = si + CHA; if (pe > nsteps) pe = nsteps;
        int m = 0;
#pragma unroll
        for (int j = 0; j < 5; ++j) {
            float hv = sZ[si - B + j];
            m = (m >> 1) | ((hv > HLO && hv < HHI) ? 16 : 0);
        }
        for (int p = si; p < pe; ++p) {
            float hv = sZ[p - B + 5];
            m |= (hv > HLO && hv < HHI) ? 32 : 0;
            if (!(m == 63 && p + 6 <= nsteps)) {
                float d = 1.f; int l = -1;       // exact rare path
#pragma unroll 1
                for (int j = 0; j < 32; ++j) {
                    int t = p + j;
                    if (t >= nsteps) break;
                    float hh = sZ[t - B];
                    float a = __fadd_rn(w2, __fmul_rn(w4_2, hh));
                    d = __fmul_rn(d, fabsf(a));
                    if (d < THRESH) { l = j + 1; break; }
                }
                if (l != 6) {
                    int i = atomicAdd(&g_anom_n, 1);
                    if (i < MAXBP) { g_anom_p[i] = p; g_anom_l[i] = (l < 0) ? BIGL : l; }
                }
            }
            m >>= 1;
        }
    }
    __threadfence();
    __syncthreads();

    if (tid == 0) {                              // phase 3: orbit walk
        int tk = atomicAdd(&g_ticket, 1);
        if (tk == (int)gridDim.x - 1) {
            __threadfence();
            int n = g_anom_n; if (n > MAXBP) n = MAXBP;
            for (int i = 1; i < n; ++i) {
                int p = g_anom_p[i], ll = g_anom_l[i], j = i - 1;
                while (j >= 0 && g_anom_p[j] > p) {
                    g_anom_p[j + 1] = g_anom_p[j]; g_anom_l[j + 1] = g_anom_l[j]; --j;
                }
                g_anom_p[j + 1] = p; g_anom_l[j + 1] = ll;
            }
            int pos = 0, K = 0;
            for (int i = 0; i < n && K < MAXBP; ++i) {
                int p = g_anom_p[i];
                if (p < pos) continue;
                if ((p - pos) % 6 != 0) continue;
                int ll = g_anom_l[i];
                g_P[K] = p;
                if (ll >= BIGL) { g_Q[K] = 0x7fffffff; ++K; break; }
                g_Q[K] = p + ll; pos = p + ll; ++K;
            }
            g_K = K;
            g_anom_n = 0;
            g_ticket = 0;
            g_C[0] = w2; g_C[1] = w4_2;
            g_C[2] = 1.f - w1 * w1;
            g_C[3] = 1.f - w2 * w2;
            g_C[4] = -2.f * w1 * (1.f - w1 * w1);
            g_C[5] = -2.f * w2 * (1.f - w2 * w2);
        }
    }
}

// window [ws, we] containing step s.
__device__ __forceinline__ void wse(int s, int& ws, int& we) {
    int K = g_K;
    if (K == 0 || s < g_P[0]) { ws = s - s % 6; we = ws + 5; return; }
    int lo = 0, hi = K - 1;
    while (lo < hi) {
        int mid = (lo + hi + 1) >> 1;
        if (g_P[mid] <= s) lo = mid; else hi = mid - 1;
    }
    int q = g_Q[lo];
    if (s < q) { ws = g_P[lo]; we = q - 1; return; }
    int r = s - q;
    ws = q + (r - r % 6); we = ws + 5;
}

#define JH_STEP(x, h, a)                                              \
    do {                                                              \
        float g3 = 2.f * (h);                                         \
        H00 = fmaf((a), H00, (x) * d2t1);                             \
        H01 = fmaf((a), H01, dt2 * J0);                               \
        H02 = (a) * H02;                                              \
        H03 = fmaf((a), H03, g3 * J0);                                \
        H11 = fmaf((a), H11, fmaf(2.f * dt2, J1, (h) * d2t2));        \
        H12 = fmaf((a), H12, dt2 * J2);                               \
        H13 = fmaf((a), H13, fmaf(dt2, J3, g3 * J1));                 \
        H22 = (a) * H22;                                              \
        H23 = fmaf((a), H23, g3 * J2);                                \
        H33 = fmaf((a), H33, (2.f * g3) * J3);                        \
        J0 = fmaf((a), J0, (x) * dt1);                                \
        J1 = fmaf((a), J1, (h) * dt2);                                \
        J2 = fmaf((a), J2, (x) * (x));                                \
        J3 = fmaf((a), J3, (h) * (h));                                \
    } while (0)

// ============================================================================
// k4: persistent grid, R7 per-tile body (one step/thread, masked-6 rebuild,
// SLOT-swizzled H staging, direct J stores).
// ============================================================================
__global__ __launch_bounds__(KBLK, BPSM) void k4_main(const float* __restrict__ X,
                                                      const float* __restrict__ Z,
                                                      float* __restrict__ outJ,
                                                      float* __restrict__ outH,
                                                      int T, int ntiles) {
    __shared__ float  sX4[NIN];
    __shared__ float  sZ4[NIN];
    __shared__ float4 sH4[NT * 4];               // 16 KB, swizzled slots
    int nsteps = T - 1;
    int tid = threadIdx.x;

    if (blockIdx.x == 0 && tid == 0) {           // row 0 of J and H = 0
        ((float4*)outJ)[0] = make_float4(0, 0, 0, 0);
        float4 z4 = make_float4(0, 0, 0, 0);
        ((float4*)outH)[0] = z4; ((float4*)outH)[1] = z4;
        ((float4*)outH)[2] = z4; ((float4*)outH)[3] = z4;
    }

    // constants hoisted out of the tile loop
    float w2   = g_C[0], w4_2 = g_C[1];
    float dt1  = g_C[2], dt2  = g_C[3];
    float d2t1 = g_C[4], d2t2 = g_C[5];

    for (int tile = blockIdx.x; tile < ntiles; tile += gridDim.x) {
        int s0 = tile * NT;

        // stage X/Z coalesced (2 iters)
#pragma unroll
        for (int k = 0; k < 2; ++k) {
            int i = tid + k * KBLK;
            if (i < NIN) {
                int t = s0 - HALO4 + i;
                float xv = 0.f, hv = 0.f;
                if (t >= 0 && t < nsteps) { xv = X[t]; hv = Z[t]; }
                sX4[i] = xv; sZ4[i] = hv;
            }
        }
        __syncthreads();

        int s = s0 + tid;
        if (s < nsteps) {
            int ws, we; wse(s, ws, we);
            float keep = (s == we) ? 0.f : 1.f;  // reset step emits zeros

            float J0 = 0, J1 = 0, J2 = 0, J3 = 0;
            float H00 = 0, H01 = 0, H02 = 0, H03 = 0, H11 = 0;
            float H12 = 0, H13 = 0, H22 = 0, H23 = 0, H33 = 0;

            if (ws >= s - 5) {
                // hot path: exactly 6 straight-line steps t = s-5..s; steps
                // with t < ws masked to identity (accumulators 0, inputs 0).
                int jmin = ws - (s - 5);         // 0..5
#pragma unroll
                for (int j = 0; j < 6; ++j) {
                    int li = tid + HALO4 - 5 + j;    // >= 3, always in-range
                    float msk = (j >= jmin) ? 1.f : 0.f;
                    float x = sX4[li] * msk;
                    float h = sZ4[li] * msk;
                    float a = __fadd_rn(w2, __fmul_rn(w4_2, h));
                    JH_STEP(x, h, a);
                }
            } else {
                // rare long window
#pragma unroll 1
                for (int t = ws; t <= s; ++t) {
                    int li = t - s0 + HALO4;
                    float x, h;
                    if (li >= 0) { x = sX4[li]; h = sZ4[li]; }
                    else         { x = X[t];    h = Z[t];   }
                    float a = __fadd_rn(w2, __fmul_rn(w4_2, h));
                    JH_STEP(x, h, a);
                }
            }

            J0 *= keep; J1 *= keep; J2 *= keep; J3 *= keep;
            H00 *= keep; H01 *= keep; H02 *= keep; H03 *= keep; H11 *= keep;
            H12 *= keep; H13 *= keep; H22 *= keep; H23 *= keep; H33 *= keep;

            ((float4*)outJ)[s + 1] = make_float4(J0, J1, J2, J3);
            int i0 = tid * 4;                    // stage H, swizzled
            sH4[SLOT(i0 + 0)] = make_float4(H00, H01, H02, H03);
            sH4[SLOT(i0 + 1)] = make_float4(H01, H11, H12, H13);
            sH4[SLOT(i0 + 2)] = make_float4(H02, H12, H22, H23);
            sH4[SLOT(i0 + 3)] = make_float4(H03, H13, H23, H33);
        }
        __syncthreads();

        int cnt = nsteps - s0; if (cnt > NT) cnt = NT;
        if (cnt < 0) cnt = 0;
        float4* Hout = (float4*)outH + (size_t)(s0 + 1) * 4;
#pragma unroll
        for (int k = 0; k < 4; ++k) {            // coalesced H stream
            int i = tid + k * KBLK;
            if (i < cnt * 4) Hout[i] = sH4[SLOT(i)];
        }
        // no extra sync needed: next iteration's staging writes sX4/sZ4 only,
        // and the post-stage __syncthreads orders it before the next compute.
    }
}

extern "C" void kernel_launch(void* const* d_in, const int* in_sizes, int n_in,
                              void* d_out, int out_size) {
    const float* X  = (const float*)d_in[0];
    const float* pr = (const float*)d_in[1];
    int T = in_sizes[0];
    float* out = (float*)d_out;
    float* Z = out;                        // [T]
    float* J = out + (size_t)T;            // [T,4]
    float* H = out + (size_t)5 * T;        // [T,4,4]

    int nsteps = T - 1;
    int gA = (nsteps + TILE - 1) / TILE;
    kA<<<gA, BLKA>>>(X, pr, Z, T);
    int ntiles = (nsteps + NT - 1) / NT;
    int gB = BPSM * NSM; if (gB > ntiles) gB = ntiles;
    k4_main<<<gB, KBLK>>>(X, Z, J, H, T, ntiles);
}

// round 15
// speedup vs baseline: 1.0118x; 1.0118x over previous
#include <cuda_runtime.h>
#include <stdint.h>
#include <math.h>

#define THRESH 1e-4f
#define MAXBP  8192
#define BIGL   0x40000000

// ---- kA config ----
#define BLKA 256
#define CHA  9                      // odd stride -> conflict-free smem chain reads
#define WUP  24
#define TILE (BLKA*CHA)             // 2304
#define XN   (TILE + WUP + 32)      // 2360
#define SZN  (TILE + 32)            // 2336
// box-screen constants: TH^(1/6)*0.997 and TH^(1/5)*1.02
#define C6BOX 0.212742f
#define C5BOX 0.161659f

// ---- k4 config ----
#define KBLK  256
#define NT    256
#define HALO4 8
#define NIN   (NT + HALO4)
#define SLOT(i) ((i) ^ (((i) >> 3) & 7))   // float4-slot swizzle (verified)

// Scratch (no allocations); zero-init first run, self-reset for graph replays.
__device__ int g_anom_n = 0;
__device__ int g_ticket = 0;
__device__ int g_anom_p[MAXBP];
__device__ int g_anom_l[MAXBP];
__device__ int g_K;
__device__ int g_P[MAXBP];
__device__ int g_Q[MAXBP];
__device__ float g_C[8];            // w2, w4_2, dt1, dt2, d2t1, d2t2

// ============================================================================
// kA: fused Z-scan + box-screened anomaly scan + orbit walk (R14-proven).
// ============================================================================
__global__ __launch_bounds__(BLKA) void kA(const float* __restrict__ X,
                                           const float* __restrict__ pr,
                                           float* __restrict__ Z, int T) {
    __shared__ float sCC[XN];
    __shared__ float sZ[SZN];
    __shared__ float sC[4];
    int nsteps = T - 1;
    int B = blockIdx.x * TILE;
    int tid = threadIdx.x;

    if (tid == 0) {                 // tanh(double) ONCE per block
        sC[0] = (float)tanh((double)pr[0]);
        sC[1] = (float)tanh((double)pr[1]);
        sC[2] = pr[2];
        sC[3] = pr[3];
    }
    __syncthreads();
    float w1 = sC[0], w2 = sC[1], w3 = sC[2], w4 = sC[3];
    float w4_2 = 2.0f * w4;

    for (int i = tid; i < XN; i += BLKA) {       // stage cc coalesced, 0-padded
        int t = B - WUP + i;
        float x = (t >= 0 && t < T) ? X[t] : 0.f;
        sCC[i] = fmaf(w3, x * x, w1 * x);
    }
    __syncthreads();

    // ---- phase 1: fixed-trip h chain (cc=0 pad keeps h exactly 0) ----
    {
        int base = tid * CHA;
        float h = 0.f;
#pragma unroll
        for (int j = 0; j < WUP; ++j) {
            float u = fmaf(w4, h, w2);
            h = fmaf(h, u, sCC[base + j]);
        }
        sZ[base] = h;
#pragma unroll
        for (int j = 0; j < CHA; ++j) {
            float u = fmaf(w4, h, w2);
            h = fmaf(h, u, sCC[base + WUP + j]);
            sZ[base + 1 + j] = h;
        }
        if (tid == BLKA - 1) {                   // 31-step halo
#pragma unroll
            for (int j = 0; j < 31; ++j) {
                float u = fmaf(w4, h, w2);
                h = fmaf(h, u, sCC[base + WUP + CHA + j]);
                sZ[base + CHA + 1 + j] = h;
            }
        }
    }
    __syncthreads();

    if (B == 0 && tid == 0) Z[0] = 0.f;          // coalesced Z writeout
    for (int i = tid; i < TILE; i += BLKA) {
        int g = B + 1 + i;
        if (g <= nsteps) Z[g] = sZ[1 + i];
    }

    // ---- phase 2: box-screened anomaly scan ----
    float HHI, HLO;
    if (w4_2 > 0.f) { HHI = (C6BOX - w2) / w4_2; HLO = (C5BOX - w2) / w4_2; }
    else            { HHI = -1e30f; HLO = 1e30f; }
    int si = B + tid * CHA;
    if (si < nsteps) {
        int pe = si + CHA; if (pe > nsteps) pe = nsteps;
        int m = 0;
#pragma unroll
        for (int j = 0; j < 5; ++j) {
            float hv = sZ[si - B + j];
            m = (m >> 1) | ((hv > HLO && hv < HHI) ? 16 : 0);
        }
        for (int p = si; p < pe; ++p) {
            float hv = sZ[p - B + 5];
            m |= (hv > HLO && hv < HHI) ? 32 : 0;
            if (!(m == 63 && p + 6 <= nsteps)) {
                float d = 1.f; int l = -1;       // exact rare path
#pragma unroll 1
                for (int j = 0; j < 32; ++j) {
                    int t = p + j;
                    if (t >= nsteps) break;
                    float hh = sZ[t - B];
                    float a = __fadd_rn(w2, __fmul_rn(w4_2, hh));
                    d = __fmul_rn(d, fabsf(a));
                    if (d < THRESH) { l = j + 1; break; }
                }
                if (l != 6) {
                    int i = atomicAdd(&g_anom_n, 1);
                    if (i < MAXBP) { g_anom_p[i] = p; g_anom_l[i] = (l < 0) ? BIGL : l; }
                }
            }
            m >>= 1;
        }
    }
    __threadfence();
    __syncthreads();

    if (tid == 0) {                              // phase 3: orbit walk
        int tk = atomicAdd(&g_ticket, 1);
        if (tk == (int)gridDim.x - 1) {
            __threadfence();
            int n = g_anom_n; if (n > MAXBP) n = MAXBP;
            for (int i = 1; i < n; ++i) {
                int p = g_anom_p[i], ll = g_anom_l[i], j = i - 1;
                while (j >= 0 && g_anom_p[j] > p) {
                    g_anom_p[j + 1] = g_anom_p[j]; g_anom_l[j + 1] = g_anom_l[j]; --j;
                }
                g_anom_p[j + 1] = p; g_anom_l[j + 1] = ll;
            }
            int pos = 0, K = 0;
            for (int i = 0; i < n && K < MAXBP; ++i) {
                int p = g_anom_p[i];
                if (p < pos) continue;
                if ((p - pos) % 6 != 0) continue;
                int ll = g_anom_l[i];
                g_P[K] = p;
                if (ll >= BIGL) { g_Q[K] = 0x7fffffff; ++K; break; }
                g_Q[K] = p + ll; pos = p + ll; ++K;
            }
            g_K = K;
            g_anom_n = 0;
            g_ticket = 0;
            g_C[0] = w2; g_C[1] = w4_2;
            g_C[2] = 1.f - w1 * w1;
            g_C[3] = 1.f - w2 * w2;
            g_C[4] = -2.f * w1 * (1.f - w1 * w1);
            g_C[5] = -2.f * w2 * (1.f - w2 * w2);
        }
    }
}

// full window lookup (rare path; only used when K>0 and s >= P[0])
__device__ __noinline__ void wse_full(int s, int& ws, int& we) {
    int K = g_K;
    int lo = 0, hi = K - 1;
    while (lo < hi) {
        int mid = (lo + hi + 1) >> 1;
        if (g_P[mid] <= s) lo = mid; else hi = mid - 1;
    }
    int q = g_Q[lo];
    if (s < q) { ws = g_P[lo]; we = q - 1; return; }
    int r = s - q;
    ws = q + (r - r % 6); we = ws + 5;
}

#define JH_STEP(x, h, a)                                              \
    do {                                                              \
        float g3 = 2.f * (h);                                         \
        H00 = fmaf((a), H00, (x) * d2t1);                             \
        H01 = fmaf((a), H01, dt2 * J0);                               \
        H02 = (a) * H02;                                              \
        H03 = fmaf((a), H03, g3 * J0);                                \
        H11 = fmaf((a), H11, fmaf(2.f * dt2, J1, (h) * d2t2));        \
        H12 = fmaf((a), H12, dt2 * J2);                               \
        H13 = fmaf((a), H13, fmaf(dt2, J3, g3 * J1));                 \
        H22 = (a) * H22;                                              \
        H23 = fmaf((a), H23, g3 * J2);                                \
        H33 = fmaf((a), H33, (2.f * g3) * J3);                        \
        J0 = fmaf((a), J0, (x) * dt1);                                \
        J1 = fmaf((a), J1, (h) * dt2);                                \
        J2 = fmaf((a), J2, (x) * (x));                                \
        J3 = fmaf((a), J3, (h) * (h));                                \
    } while (0)

// ============================================================================
// k4: R7 structure, MIO-slimmed: interleaved float2 X/Z staging (LDS.64),
// smem-broadcast breakpoint header, SLOT-swizzled H staging, direct J.
// ============================================================================
__global__ __launch_bounds__(KBLK) void k4_main(const float* __restrict__ X,
                                                const float* __restrict__ Z,
                                                float* __restrict__ outJ,
                                                float* __restrict__ outH, int T) {
    __shared__ float2 sXZ[NIN];                  // interleaved (x, h)
    __shared__ float4 sH4[NT * 4];               // 16 KB, swizzled slots
    __shared__ int    sKP[2];                    // g_K, g_P[0]
    int nsteps = T - 1;
    int s0 = blockIdx.x * NT;
    int tid = threadIdx.x;

    if (blockIdx.x == 0 && tid == 0) {           // row 0 of J and H = 0
        ((float4*)outJ)[0] = make_float4(0, 0, 0, 0);
        float4 z4 = make_float4(0, 0, 0, 0);
        ((float4*)outH)[0] = z4; ((float4*)outH)[1] = z4;
        ((float4*)outH)[2] = z4; ((float4*)outH)[3] = z4;
    }
    if (tid == 0) {
        int K = g_K;
        sKP[0] = K;
        sKP[1] = K ? g_P[0] : 0x7fffffff;
    }

    for (int i = tid; i < NIN; i += KBLK) {      // stage X/Z interleaved
        int t = s0 - HALO4 + i;
        float xv = 0.f, hv = 0.f;
        if (t >= 0 && t < nsteps) { xv = X[t]; hv = Z[t]; }
        sXZ[i] = make_float2(xv, hv);
    }
    __syncthreads();

    int s = s0 + tid;
    if (s < nsteps) {
        float w2   = g_C[0], w4_2 = g_C[1];
        float dt1  = g_C[2], dt2  = g_C[3];
        float d2t1 = g_C[4], d2t2 = g_C[5];

        int ws, we;
        if (sKP[0] == 0 || s < sKP[1]) {         // common case: pure arithmetic
            ws = s - s % 6; we = ws + 5;
        } else {
            wse_full(s, ws, we);
        }
        float keep = (s == we) ? 0.f : 1.f;      // reset step emits zeros

        float J0 = 0, J1 = 0, J2 = 0, J3 = 0;
        float H00 = 0, H01 = 0, H02 = 0, H03 = 0, H11 = 0;
        float H12 = 0, H13 = 0, H22 = 0, H23 = 0, H33 = 0;

        if (ws >= s - 5) {
            // hot path: exactly 6 straight-line steps t = s-5..s; steps with
            // t < ws masked to identity (accumulators 0, inputs zeroed).
            int jmin = ws - (s - 5);             // 0..5
#pragma unroll
            for (int j = 0; j < 6; ++j) {
                int li = tid + HALO4 - 5 + j;    // >= 3, always in-range
                float msk = (j >= jmin) ? 1.f : 0.f;
                float2 xz = sXZ[li];             // one LDS.64
                float x = xz.x * msk;
                float h = xz.y * msk;
                float a = __fadd_rn(w2, __fmul_rn(w4_2, h));
                JH_STEP(x, h, a);
            }
        } else {
            // rare long window
#pragma unroll 1
            for (int t = ws; t <= s; ++t) {
                int li = t - s0 + HALO4;
                float x, h;
                if (li >= 0) { float2 xz = sXZ[li]; x = xz.x; h = xz.y; }
                else         { x = X[t]; h = Z[t]; }
                float a = __fadd_rn(w2, __fmul_rn(w4_2, h));
                JH_STEP(x, h, a);
            }
        }

        J0 *= keep; J1 *= keep; J2 *= keep; J3 *= keep;
        H00 *= keep; H01 *= keep; H02 *= keep; H03 *= keep; H11 *= keep;
        H12 *= keep; H13 *= keep; H22 *= keep; H23 *= keep; H33 *= keep;

        ((float4*)outJ)[s + 1] = make_float4(J0, J1, J2, J3);
        int i0 = tid * 4;                        // stage H, swizzled
        sH4[SLOT(i0 + 0)] = make_float4(H00, H01, H02, H03);
        sH4[SLOT(i0 + 1)] = make_float4(H01, H11, H12, H13);
        sH4[SLOT(i0 + 2)] = make_float4(H02, H12, H22, H23);
        sH4[SLOT(i0 + 3)] = make_float4(H03, H13, H23, H33);
    }
    __syncthreads();

    int cnt = nsteps - s0; if (cnt > NT) cnt = NT;
    if (cnt < 0) cnt = 0;
    float4* Hout = (float4*)outH + (size_t)(s0 + 1) * 4;
#pragma unroll
    for (int k = 0; k < 4; ++k) {                // coalesced H stream
        int i = tid + k * KBLK;
        if (i < cnt * 4) Hout[i] = sH4[SLOT(i)];
    }
}

extern "C" void kernel_launch(void* const* d_in, const int* in_sizes, int n_in,
                              void* d_out, int out_size) {
    const float* X  = (const float*)d_in[0];
    const float* pr = (const float*)d_in[1];
    int T = in_sizes[0];
    float* out = (float*)d_out;
    float* Z = out;                        // [T]
    float* J = out + (size_t)T;            // [T,4]
    float* H = out + (size_t)5 * T;        // [T,4,4]

    int nsteps = T - 1;
    int gA = (nsteps + TILE - 1) / TILE;
    kA<<<gA, BLKA>>>(X, pr, Z, T);
    int gB = (nsteps + NT - 1) / NT;
    k4_main<<<gB, KBLK>>>(X, Z, J, H, T);
}

// round 16
// speedup vs baseline: 1.0559x; 1.0435x over previous
#include <cuda_runtime.h>
#include <stdint.h>
#include <math.h>

#define THRESH 1e-4f
#define MAXBP  8192
#define BIGL   0x40000000

#define NBLK 256                    // threads per block (both phases)
#define G    592                    // grid: 4/SM x 148 SMs, co-resident

// ---- phase A (Z scan + anomaly) config ----
#define CHA  7                      // odd stride -> conflict-free smem chain reads
#define WUP  24
#define TILEA (NBLK*CHA)            // 1792
#define XNA  (TILEA + WUP + 32)     // 1848
#define SZNA (TILEA + 32)           // 1824
// box-screen constants: TH^(1/6)*0.997 and TH^(1/5)*1.02
#define C6BOX 0.212742f
#define C5BOX 0.161659f

// ---- phase B (J/H emit) config ----
#define NT    256
#define HALO4 8
#define NIN   (NT + HALO4)
#define SLOT(i) ((i) ^ (((i) >> 3) & 7))   // float4-slot swizzle (verified)

// Scratch (no allocations). g_barA/g_release are MONOTONIC (replay-safe).
__device__ int g_anom_n = 0;
__device__ int g_barA = 0;
__device__ volatile int g_release = 0;
__device__ int g_anom_p[MAXBP];
__device__ int g_anom_l[MAXBP];
__device__ int g_K;
__device__ int g_P[MAXBP];
__device__ int g_Q[MAXBP];
__device__ float g_C[8];            // w2, w4_2, dt1, dt2, d2t1, d2t2

#define JH_STEP(x, h, a)                                              \
    do {                                                              \
        float g3 = 2.f * (h);                                         \
        H00 = fmaf((a), H00, (x) * d2t1);                             \
        H01 = fmaf((a), H01, dt2 * J0);                               \
        H02 = (a) * H02;                                              \
        H03 = fmaf((a), H03, g3 * J0);                                \
        H11 = fmaf((a), H11, fmaf(2.f * dt2, J1, (h) * d2t2));        \
        H12 = fmaf((a), H12, dt2 * J2);                               \
        H13 = fmaf((a), H13, fmaf(dt2, J3, g3 * J1));                 \
        H22 = (a) * H22;                                              \
        H23 = fmaf((a), H23, g3 * J2);                                \
        H33 = fmaf((a), H33, (2.f * g3) * J3);                        \
        J0 = fmaf((a), J0, (x) * dt1);                                \
        J1 = fmaf((a), J1, (h) * dt2);                                \
        J2 = fmaf((a), J2, (x) * (x));                                \
        J3 = fmaf((a), J3, (h) * (h));                                \
    } while (0)

// full window lookup (rare path; only when K>0 and s >= P[0])
__device__ __noinline__ void wse_full(int s, int& ws, int& we) {
    int K = g_K;
    int lo = 0, hi = K - 1;
    while (lo < hi) {
        int mid = (lo + hi + 1) >> 1;
        if (g_P[mid] <= s) lo = mid; else hi = mid - 1;
    }
    int q = g_Q[lo];
    if (s < q) { ws = g_P[lo]; we = q - 1; return; }
    int r = s - q;
    ws = q + (r - r % 6); we = ws + 5;
}

// ============================================================================
// Fused kernel: phase A (Z + anomalies) -> grid barrier + walk -> phase B (J/H)
// ============================================================================
__global__ __launch_bounds__(NBLK, 4) void kF(const float* __restrict__ X,
                                              const float* __restrict__ pr,
                                              float* __restrict__ Z,
                                              float* __restrict__ outJ,
                                              float* __restrict__ outH,
                                              int T, int ntA, int ntB) {
    __shared__ float  sCC[XNA];
    __shared__ float  sZ[SZNA];
    __shared__ float2 sXZ[NIN];
    __shared__ float4 sH4[NT * 4];
    __shared__ float  sC[4];
    __shared__ float  sC2[6];
    __shared__ int    sKP[2];
    int nsteps = T - 1;
    int tid = threadIdx.x;

    if (blockIdx.x == 0 && tid == 0) {           // row 0 of J and H = 0
        ((float4*)outJ)[0] = make_float4(0, 0, 0, 0);
        float4 z4 = make_float4(0, 0, 0, 0);
        ((float4*)outH)[0] = z4; ((float4*)outH)[1] = z4;
        ((float4*)outH)[2] = z4; ((float4*)outH)[3] = z4;
    }
    if (tid == 0) {                              // tanh(double) once per block
        sC[0] = (float)tanh((double)pr[0]);
        sC[1] = (float)tanh((double)pr[1]);
        sC[2] = pr[2];
        sC[3] = pr[3];
    }
    __syncthreads();
    float w1 = sC[0], w2 = sC[1], w3 = sC[2], w4 = sC[3];
    float w4_2 = 2.0f * w4;

    // ======================= PHASE A ========================================
    for (int a = blockIdx.x; a < ntA; a += G) {
        int B = a * TILEA;

        for (int i = tid; i < XNA; i += NBLK) {  // stage cc coalesced, 0-padded
            int t = B - WUP + i;
            float x = (t >= 0 && t < T) ? X[t] : 0.f;
            sCC[i] = fmaf(w3, x * x, w1 * x);
        }
        __syncthreads();

        {   // fixed-trip h chain (cc=0 pad keeps h exactly 0)
            int base = tid * CHA;
            float h = 0.f;
#pragma unroll
            for (int j = 0; j < WUP; ++j) {
                float u = fmaf(w4, h, w2);
                h = fmaf(h, u, sCC[base + j]);
            }
            sZ[base] = h;
#pragma unroll
            for (int j = 0; j < CHA; ++j) {
                float u = fmaf(w4, h, w2);
                h = fmaf(h, u, sCC[base + WUP + j]);
                sZ[base + 1 + j] = h;
            }
            if (tid == NBLK - 1) {               // 31-step halo
#pragma unroll
                for (int j = 0; j < 31; ++j) {
                    float u = fmaf(w4, h, w2);
                    h = fmaf(h, u, sCC[base + WUP + CHA + j]);
                    sZ[base + CHA + 1 + j] = h;
                }
            }
        }
        __syncthreads();

        if (B == 0 && tid == 0) Z[0] = 0.f;      // coalesced Z writeout
        for (int i = tid; i < TILEA; i += NBLK) {
            int g = B + 1 + i;
            if (g <= nsteps) Z[g] = sZ[1 + i];
        }

        // box-screened anomaly scan
        float HHI, HLO;
        if (w4_2 > 0.f) { HHI = (C6BOX - w2) / w4_2; HLO = (C5BOX - w2) / w4_2; }
        else            { HHI = -1e30f; HLO = 1e30f; }
        int si = B + tid * CHA;
        if (si < nsteps) {
            int pe = si + CHA; if (pe > nsteps) pe = nsteps;
            int m = 0;
#pragma unroll
            for (int j = 0; j < 5; ++j) {
                float hv = sZ[si - B + j];
                m = (m >> 1) | ((hv > HLO && hv < HHI) ? 16 : 0);
            }
            for (int p = si; p < pe; ++p) {
                float hv = sZ[p - B + 5];
                m |= (hv > HLO && hv < HHI) ? 32 : 0;
                if (!(m == 63 && p + 6 <= nsteps)) {
                    float d = 1.f; int l = -1;   // exact rare path
#pragma unroll 1
                    for (int j = 0; j < 32; ++j) {
                        int t = p + j;
                        if (t >= nsteps) break;
                        float hh = sZ[t - B];
                        float aa = __fadd_rn(w2, __fmul_rn(w4_2, hh));
                        d = __fmul_rn(d, fabsf(aa));
                        if (d < THRESH) { l = j + 1; break; }
                    }
                    if (l != 6) {
                        int i = atomicAdd(&g_anom_n, 1);
                        if (i < MAXBP) { g_anom_p[i] = p; g_anom_l[i] = (l < 0) ? BIGL : l; }
                    }
                }
                m >>= 1;
            }
        }
        __syncthreads();
    }
    __threadfence();                             // publish Z + anomalies
    __syncthreads();

    // ======================= GRID BARRIER + WALK ============================
    if (tid == 0) {
        int t = atomicAdd(&g_barA, 1);
        int target = (t / G) * G + G;            // epoch end (monotonic)
        if (t == target - 1) {
            // last arriver: walk the reset orbit, export constants
            __threadfence();
            int n = g_anom_n; if (n > MAXBP) n = MAXBP;
            for (int i = 1; i < n; ++i) {        // tiny insertion sort
                int p = g_anom_p[i], ll = g_anom_l[i], j = i - 1;
                while (j >= 0 && g_anom_p[j] > p) {
                    g_anom_p[j + 1] = g_anom_p[j]; g_anom_l[j + 1] = g_anom_l[j]; --j;
                }
                g_anom_p[j + 1] = p; g_anom_l[j + 1] = ll;
            }
            int pos = 0, K = 0;
            for (int i = 0; i < n && K < MAXBP; ++i) {
                int p = g_anom_p[i];
                if (p < pos) continue;
                if ((p - pos) % 6 != 0) continue;
                int ll = g_anom_l[i];
                g_P[K] = p;
                if (ll >= BIGL) { g_Q[K] = 0x7fffffff; ++K; break; }
                g_Q[K] = p + ll; pos = p + ll; ++K;
            }
            g_K = K;
            g_anom_n = 0;                        // reset for next replay
            g_C[0] = w2; g_C[1] = w4_2;
            g_C[2] = 1.f - w1 * w1;
            g_C[3] = 1.f - w2 * w2;
            g_C[4] = -2.f * w1 * (1.f - w1 * w1);
            g_C[5] = -2.f * w2 * (1.f - w2 * w2);
            __threadfence();
            g_release = target;                  // release epoch
        } else {
            while (g_release < target) __nanosleep(64);
        }
        __threadfence();
        int K = g_K;
        sKP[0] = K;
        sKP[1] = K ? g_P[0] : 0x7fffffff;
#pragma unroll
        for (int i = 0; i < 6; ++i) sC2[i] = g_C[i];
    }
    __syncthreads();

    // ======================= PHASE B ========================================
    {
        float bw2   = sC2[0], bw4_2 = sC2[1];
        float dt1   = sC2[2], dt2   = sC2[3];
        float d2t1  = sC2[4], d2t2  = sC2[5];
        int   Khdr  = sKP[0], P0 = sKP[1];

        for (int tile = blockIdx.x; tile < ntB; tile += G) {
            int s0 = tile * NT;

            for (int i = tid; i < NIN; i += NBLK) {   // stage X/Z interleaved
                int t = s0 - HALO4 + i;
                float xv = 0.f, hv = 0.f;
                if (t >= 0 && t < nsteps) { xv = X[t]; hv = Z[t]; }
                sXZ[i] = make_float2(xv, hv);
            }
            __syncthreads();

            int s = s0 + tid;
            if (s < nsteps) {
                int ws, we;
                if (Khdr == 0 || s < P0) {       // common case: pure arithmetic
                    ws = s - s % 6; we = ws + 5;
                } else {
                    wse_full(s, ws, we);
                }
                float keep = (s == we) ? 0.f : 1.f;

                float J0 = 0, J1 = 0, J2 = 0, J3 = 0;
                float H00 = 0, H01 = 0, H02 = 0, H03 = 0, H11 = 0;
                float H12 = 0, H13 = 0, H22 = 0, H23 = 0, H33 = 0;

                if (ws >= s - 5) {
                    // hot path: 6 straight-line steps, masked to window
                    int jmin = ws - (s - 5);     // 0..5
#pragma unroll
                    for (int j = 0; j < 6; ++j) {
                        int li = tid + HALO4 - 5 + j;  // >= 3, in-range
                        float msk = (j >= jmin) ? 1.f : 0.f;
                        float2 xz = sXZ[li];           // one LDS.64
                        float x = xz.x * msk;
                        float h = xz.y * msk;
                        float aa = __fadd_rn(bw2, __fmul_rn(bw4_2, h));
                        JH_STEP(x, h, aa);
                    }
                } else {
                    // rare long window
#pragma unroll 1
                    for (int t = ws; t <= s; ++t) {
                        int li = t - s0 + HALO4;
                        float x, h;
                        if (li >= 0) { float2 xz = sXZ[li]; x = xz.x; h = xz.y; }
                        else         { x = X[t]; h = Z[t]; }
                        float aa = __fadd_rn(bw2, __fmul_rn(bw4_2, h));
                        JH_STEP(x, h, aa);
                    }
                }

                J0 *= keep; J1 *= keep; J2 *= keep; J3 *= keep;
                H00 *= keep; H01 *= keep; H02 *= keep; H03 *= keep;
                H11 *= keep; H12 *= keep; H13 *= keep; H22 *= keep;
                H23 *= keep; H33 *= keep;

                ((float4*)outJ)[s + 1] = make_float4(J0, J1, J2, J3);
                int i0 = tid * 4;                // stage H, swizzled
                sH4[SLOT(i0 + 0)] = make_float4(H00, H01, H02, H03);
                sH4[SLOT(i0 + 1)] = make_float4(H01, H11, H12, H13);
                sH4[SLOT(i0 + 2)] = make_float4(H02, H12, H22, H23);
                sH4[SLOT(i0 + 3)] = make_float4(H03, H13, H23, H33);
            }
            __syncthreads();

            int cnt = nsteps - s0; if (cnt > NT) cnt = NT;
            if (cnt < 0) cnt = 0;
            float4* Hout = (float4*)outH + (size_t)(s0 + 1) * 4;
#pragma unroll
            for (int k = 0; k < 4; ++k) {        // coalesced H stream
                int i = tid + k * NBLK;
                if (i < cnt * 4) Hout[i] = sH4[SLOT(i)];
            }
            // next iteration's stage-sync orders sH4 reuse (R14-verified)
        }
    }
}

extern "C" void kernel_launch(void* const* d_in, const int* in_sizes, int n_in,
                              void* d_out, int out_size) {
    const float* X  = (const float*)d_in[0];
    const float* pr = (const float*)d_in[1];
    int T = in_sizes[0];
    float* out = (float*)d_out;
    float* Z = out;                        // [T]
    float* J = out + (size_t)T;            // [T,4]
    float* H = out + (size_t)5 * T;        // [T,4,4]

    int nsteps = T - 1;
    int ntA = (nsteps + TILEA - 1) / TILEA;
    int ntB = (nsteps + NT - 1) / NT;
    kF<<<G, NBLK>>>(X, pr, Z, J, H, T, ntA, ntB);
}

// round 17
// speedup vs baseline: 1.0629x; 1.0066x over previous
#include <cuda_runtime.h>
#include <stdint.h>
#include <math.h>

#define THRESH 1e-4f
#define MAXBP  8192
#define BIGL   0x40000000

#define NBLK 256                    // threads per block (both phases)
#define G    888                    // grid: 6/SM x 148 SMs, co-resident

// ---- phase A (Z scan + anomaly) config ----
#define CHA  7                      // odd stride -> conflict-free smem chain reads
#define WUP  24
#define TILEA (NBLK*CHA)            // 1792
#define XNA  (TILEA + WUP + 32)     // 1848
#define SZNA (TILEA + 32)           // 1824
// box-screen constants: TH^(1/6)*0.997 and TH^(1/5)*1.02
#define C6BOX 0.212742f
#define C5BOX 0.161659f

// ---- phase B (J/H emit) config ----
#define NT    256
#define HALO4 8
#define NIN   (NT + HALO4)
#define SLOT(i) ((i) ^ (((i) >> 3) & 7))   // float4-slot swizzle (verified)

// Scratch (no allocations). g_barA/g_release are MONOTONIC (replay-safe).
__device__ int g_anom_n = 0;
__device__ int g_barA = 0;
__device__ volatile int g_release = 0;
__device__ int g_anom_p[MAXBP];
__device__ int g_anom_l[MAXBP];
__device__ int g_K;
__device__ int g_P[MAXBP];
__device__ int g_Q[MAXBP];
__device__ float g_C[8];            // w2, w4_2, dt1, dt2, d2t1, d2t2

#define JH_STEP(x, h, a)                                              \
    do {                                                              \
        float g3 = 2.f * (h);                                         \
        H00 = fmaf((a), H00, (x) * d2t1);                             \
        H01 = fmaf((a), H01, dt2 * J0);                               \
        H02 = (a) * H02;                                              \
        H03 = fmaf((a), H03, g3 * J0);                                \
        H11 = fmaf((a), H11, fmaf(2.f * dt2, J1, (h) * d2t2));        \
        H12 = fmaf((a), H12, dt2 * J2);                               \
        H13 = fmaf((a), H13, fmaf(dt2, J3, g3 * J1));                 \
        H22 = (a) * H22;                                              \
        H23 = fmaf((a), H23, g3 * J2);                                \
        H33 = fmaf((a), H33, (2.f * g3) * J3);                        \
        J0 = fmaf((a), J0, (x) * dt1);                                \
        J1 = fmaf((a), J1, (h) * dt2);                                \
        J2 = fmaf((a), J2, (x) * (x));                                \
        J3 = fmaf((a), J3, (h) * (h));                                \
    } while (0)

// full window lookup (rare path; only when K>0 and s >= P[0])
__device__ __noinline__ void wse_full(int s, int& ws, int& we) {
    int K = g_K;
    int lo = 0, hi = K - 1;
    while (lo < hi) {
        int mid = (lo + hi + 1) >> 1;
        if (g_P[mid] <= s) lo = mid; else hi = mid - 1;
    }
    int q = g_Q[lo];
    if (s < q) { ws = g_P[lo]; we = q - 1; return; }
    int r = s - q;
    ws = q + (r - r % 6); we = ws + 5;
}

// ============================================================================
// Fused kernel: phase A (Z + anomalies) -> grid barrier + walk -> phase B (J/H)
// ============================================================================
__global__ __launch_bounds__(NBLK, 6) void kF(const float* __restrict__ X,
                                              const float* __restrict__ pr,
                                              float* __restrict__ Z,
                                              float* __restrict__ outJ,
                                              float* __restrict__ outH,
                                              int T, int ntA, int ntB) {
    __shared__ float  sCC[XNA];
    __shared__ float  sZ[SZNA];
    __shared__ float2 sXZ[NIN];
    __shared__ float4 sH4[NT * 4];
    __shared__ float  sC[4];
    __shared__ float  sC2[6];
    __shared__ int    sKP[2];
    int nsteps = T - 1;
    int tid = threadIdx.x;

    if (blockIdx.x == 0 && tid == 0) {           // row 0 of J and H = 0
        ((float4*)outJ)[0] = make_float4(0, 0, 0, 0);
        float4 z4 = make_float4(0, 0, 0, 0);
        ((float4*)outH)[0] = z4; ((float4*)outH)[1] = z4;
        ((float4*)outH)[2] = z4; ((float4*)outH)[3] = z4;
    }
    if (tid == 0) {                              // tanh(double) once per block
        sC[0] = (float)tanh((double)pr[0]);
        sC[1] = (float)tanh((double)pr[1]);
        sC[2] = pr[2];
        sC[3] = pr[3];
    }
    __syncthreads();
    float w1 = sC[0], w2 = sC[1], w3 = sC[2], w4 = sC[3];
    float w4_2 = 2.0f * w4;

    // ======================= PHASE A ========================================
    for (int a = blockIdx.x; a < ntA; a += G) {
        int B = a * TILEA;

        for (int i = tid; i < XNA; i += NBLK) {  // stage cc coalesced, 0-padded
            int t = B - WUP + i;
            float x = (t >= 0 && t < T) ? X[t] : 0.f;
            sCC[i] = fmaf(w3, x * x, w1 * x);
        }
        __syncthreads();

        {   // fixed-trip h chain (cc=0 pad keeps h exactly 0)
            int base = tid * CHA;
            float h = 0.f;
#pragma unroll
            for (int j = 0; j < WUP; ++j) {
                float u = fmaf(w4, h, w2);
                h = fmaf(h, u, sCC[base + j]);
            }
            sZ[base] = h;
#pragma unroll
            for (int j = 0; j < CHA; ++j) {
                float u = fmaf(w4, h, w2);
                h = fmaf(h, u, sCC[base + WUP + j]);
                sZ[base + 1 + j] = h;
            }
            if (tid == NBLK - 1) {               // 31-step halo
#pragma unroll
                for (int j = 0; j < 31; ++j) {
                    float u = fmaf(w4, h, w2);
                    h = fmaf(h, u, sCC[base + WUP + CHA + j]);
                    sZ[base + CHA + 1 + j] = h;
                }
            }
        }
        __syncthreads();

        if (B == 0 && tid == 0) Z[0] = 0.f;      // coalesced Z writeout
        for (int i = tid; i < TILEA; i += NBLK) {
            int g = B + 1 + i;
            if (g <= nsteps) Z[g] = sZ[1 + i];
        }

        // box-screened anomaly scan
        float HHI, HLO;
        if (w4_2 > 0.f) { HHI = (C6BOX - w2) / w4_2; HLO = (C5BOX - w2) / w4_2; }
        else            { HHI = -1e30f; HLO = 1e30f; }
        int si = B + tid * CHA;
        if (si < nsteps) {
            int pe = si + CHA; if (pe > nsteps) pe = nsteps;
            int m = 0;
#pragma unroll
            for (int j = 0; j < 5; ++j) {
                float hv = sZ[si - B + j];
                m = (m >> 1) | ((hv > HLO && hv < HHI) ? 16 : 0);
            }
            for (int p = si; p < pe; ++p) {
                float hv = sZ[p - B + 5];
                m |= (hv > HLO && hv < HHI) ? 32 : 0;
                if (!(m == 63 && p + 6 <= nsteps)) {
                    float d = 1.f; int l = -1;   // exact rare path
#pragma unroll 1
                    for (int j = 0; j < 32; ++j) {
                        int t = p + j;
                        if (t >= nsteps) break;
                        float hh = sZ[t - B];
                        float aa = __fadd_rn(w2, __fmul_rn(w4_2, hh));
                        d = __fmul_rn(d, fabsf(aa));
                        if (d < THRESH) { l = j + 1; break; }
                    }
                    if (l != 6) {
                        int i = atomicAdd(&g_anom_n, 1);
                        if (i < MAXBP) { g_anom_p[i] = p; g_anom_l[i] = (l < 0) ? BIGL : l; }
                    }
                }
                m >>= 1;
            }
        }
        __syncthreads();
    }
    __threadfence();                             // publish Z + anomalies
    __syncthreads();

    // ======================= GRID BARRIER + WALK ============================
    if (tid == 0) {
        int t = atomicAdd(&g_barA, 1);
        int target = (t / G) * G + G;            // epoch end (monotonic)
        if (t == target - 1) {
            // last arriver: walk the reset orbit, export constants
            __threadfence();
            int n = g_anom_n; if (n > MAXBP) n = MAXBP;
            for (int i = 1; i < n; ++i) {        // tiny insertion sort
                int p = g_anom_p[i], ll = g_anom_l[i], j = i - 1;
                while (j >= 0 && g_anom_p[j] > p) {
                    g_anom_p[j + 1] = g_anom_p[j]; g_anom_l[j + 1] = g_anom_l[j]; --j;
                }
                g_anom_p[j + 1] = p; g_anom_l[j + 1] = ll;
            }
            int pos = 0, K = 0;
            for (int i = 0; i < n && K < MAXBP; ++i) {
                int p = g_anom_p[i];
                if (p < pos) continue;
                if ((p - pos) % 6 != 0) continue;
                int ll = g_anom_l[i];
                g_P[K] = p;
                if (ll >= BIGL) { g_Q[K] = 0x7fffffff; ++K; break; }
                g_Q[K] = p + ll; pos = p + ll; ++K;
            }
            g_K = K;
            g_anom_n = 0;                        // reset for next replay
            g_C[0] = w2; g_C[1] = w4_2;
            g_C[2] = 1.f - w1 * w1;
            g_C[3] = 1.f - w2 * w2;
            g_C[4] = -2.f * w1 * (1.f - w1 * w1);
            g_C[5] = -2.f * w2 * (1.f - w2 * w2);
            __threadfence();
            g_release = target;                  // release epoch
        } else {
            while (g_release < target) __nanosleep(64);
        }
        __threadfence();
        int K = g_K;
        sKP[0] = K;
        sKP[1] = K ? g_P[0] : 0x7fffffff;
#pragma unroll
        for (int i = 0; i < 6; ++i) sC2[i] = g_C[i];
    }
    __syncthreads();

    // ======================= PHASE B ========================================
    {
        float bw2   = sC2[0], bw4_2 = sC2[1];
        float dt1   = sC2[2], dt2   = sC2[3];
        float d2t1  = sC2[4], d2t2  = sC2[5];
        int   Khdr  = sKP[0], P0 = sKP[1];

        for (int tile = blockIdx.x; tile < ntB; tile += G) {
            int s0 = tile * NT;

            for (int i = tid; i < NIN; i += NBLK) {   // stage X/Z interleaved
                int t = s0 - HALO4 + i;
                float xv = 0.f, hv = 0.f;
                if (t >= 0 && t < nsteps) { xv = X[t]; hv = Z[t]; }
                sXZ[i] = make_float2(xv, hv);
            }
            __syncthreads();

            int s = s0 + tid;
            if (s < nsteps) {
                int ws, we;
                if (Khdr == 0 || s < P0) {       // common case: pure arithmetic
                    ws = s - s % 6; we = ws + 5;
                } else {
                    wse_full(s, ws, we);
                }
                float keep = (s == we) ? 0.f : 1.f;

                float J0 = 0, J1 = 0, J2 = 0, J3 = 0;
                float H00 = 0, H01 = 0, H02 = 0, H03 = 0, H11 = 0;
                float H12 = 0, H13 = 0, H22 = 0, H23 = 0, H33 = 0;

                if (ws >= s - 5) {
                    // hot path: 6 straight-line steps, masked to window
                    int jmin = ws - (s - 5);     // 0..5
#pragma unroll
                    for (int j = 0; j < 6; ++j) {
                        int li = tid + HALO4 - 5 + j;  // >= 3, in-range
                        float msk = (j >= jmin) ? 1.f : 0.f;
                        float2 xz = sXZ[li];           // one LDS.64
                        float x = xz.x * msk;
                        float h = xz.y * msk;
                        float aa = __fadd_rn(bw2, __fmul_rn(bw4_2, h));
                        JH_STEP(x, h, aa);
                    }
                } else {
                    // rare long window
#pragma unroll 1
                    for (int t = ws; t <= s; ++t) {
                        int li = t - s0 + HALO4;
                        float x, h;
                        if (li >= 0) { float2 xz = sXZ[li]; x = xz.x; h = xz.y; }
                        else         { x = X[t]; h = Z[t]; }
                        float aa = __fadd_rn(bw2, __fmul_rn(bw4_2, h));
                        JH_STEP(x, h, aa);
                    }
                }

                J0 *= keep; J1 *= keep; J2 *= keep; J3 *= keep;
                H00 *= keep; H01 *= keep; H02 *= keep; H03 *= keep;
                H11 *= keep; H12 *= keep; H13 *= keep; H22 *= keep;
                H23 *= keep; H33 *= keep;

                ((float4*)outJ)[s + 1] = make_float4(J0, J1, J2, J3);
                int i0 = tid * 4;                // stage H, swizzled
                sH4[SLOT(i0 + 0)] = make_float4(H00, H01, H02, H03);
                sH4[SLOT(i0 + 1)] = make_float4(H01, H11, H12, H13);
                sH4[SLOT(i0 + 2)] = make_float4(H02, H12, H22, H23);
                sH4[SLOT(i0 + 3)] = make_float4(H03, H13, H23, H33);
            }
            __syncthreads();

            int cnt = nsteps - s0; if (cnt > NT) cnt = NT;
            if (cnt < 0) cnt = 0;
            float4* Hout = (float4*)outH + (size_t)(s0 + 1) * 4;
#pragma unroll
            for (int k = 0; k < 4; ++k) {        // coalesced H stream
                int i = tid + k * NBLK;
                if (i < cnt * 4) Hout[i] = sH4[SLOT(i)];
            }
            // next iteration's stage-sync orders sH4 reuse (R14-verified)
        }
    }
}

extern "C" void kernel_launch(void* const* d_in, const int* in_sizes, int n_in,
                              void* d_out, int out_size) {
    const float* X  = (const float*)d_in[0];
    const float* pr = (const float*)d_in[1];
    int T = in_sizes[0];
    float* out = (float*)d_out;
    float* Z = out;                        // [T]
    float* J = out + (size_t)T;            // [T,4]
    float* H = out + (size_t)5 * T;        // [T,4,4]

    int nsteps = T - 1;
    int ntA = (nsteps + TILEA - 1) / TILEA;
    int ntB = (nsteps + NT - 1) / NT;
    kF<<<G, NBLK>>>(X, pr, Z, J, H, T, ntA, ntB);
}